// round 1
// baseline (speedup 1.0000x reference)
#include <cuda_runtime.h>

#define B 128
#define S 512
#define H 1024
#define NL 4
#define NCOL 3072      // only i,g,o gate blocks (f-gate is dead: c0 = 0)
#define KS 4           // K-split for occupancy
#define BN 32
#define BK 32

#define OUT_SH (S*B*H)            // 67108864
#define OUT_SC (S*B*H + NL*B*H)   // 67633152

// ---------------- scratch (device globals; no allocation allowed) ----------
__device__ float g_xt[2][B*H];          // ping-pong layer activations (sorted order)
__device__ float g_part[KS][B*NCOL];    // K-split GEMM partials
__device__ int   g_len[B];
__device__ int   g_rank[B];             // unsort_idx: position of row b in sorted order
__device__ int   g_sorted[B];
__device__ int   g_tok0[B];             // token at t=0 of sorted row i
__device__ int   g_bslast;

// ---------------- packed fp32x2 FMA (PTX-only on Blackwell) ----------------
__device__ __forceinline__ void fma2(unsigned long long &d,
                                     unsigned long long a,
                                     unsigned long long b) {
    asm("fma.rn.f32x2 %0, %1, %2, %0;" : "+l"(d) : "l"(a), "l"(b));
}

// ---------------- 1) lengths: one warp per batch row ----------------------
__global__ void len_kernel(const int* __restrict__ x) {
    int b = blockIdx.x, lane = threadIdx.x;
    int cnt = 0;
    #pragma unroll
    for (int s = lane; s < S; s += 32) cnt += (x[b*S + s] > 0);
    #pragma unroll
    for (int o = 16; o; o >>= 1) cnt += __shfl_down_sync(0xffffffffu, cnt, o);
    if (lane == 0) g_len[b] = cnt;
}

// ---------------- 2) stable descending argsort of 128 lengths -------------
__global__ void sort_kernel(const int* __restrict__ x) {
    __shared__ int slen[B];
    __shared__ int ssort[B];
    int b = threadIdx.x;
    slen[b] = g_len[b];
    __syncthreads();
    int lb = slen[b];
    int rank = 0, bs = 0;
    #pragma unroll 8
    for (int i = 0; i < B; i++) {
        int li = slen[i];
        rank += (li > lb) || (li == lb && i < b);
        bs += (li >= S);
    }
    g_rank[b] = rank;      // unsort index
    ssort[rank] = b;
    if (b == 0) g_bslast = bs;
    __syncthreads();
    int src = ssort[b];
    g_sorted[b] = src;
    g_tok0[b] = x[src * S];   // t = 0 token of sorted row b
}

// ---------------- 3) embedding gather (sorted order) ----------------------
__global__ void embed_kernel(const float* __restrict__ emb) {
    int i = blockIdx.x;
    int t = threadIdx.x;       // 256 threads, 1 float4 each (H = 1024)
    int tok = g_tok0[i];
    *(float4*)&g_xt[0][i*H + t*4] = *(const float4*)&emb[tok*H + t*4];
}

// ---------------- 4) GEMM: gates[b][n] = xt @ W_ih[rows i,g,o]^T ----------
// virtual column n in [0,3072): n<1024 -> i (j=n), else g/o (j=n+1024)
__global__ __launch_bounds__(256) void gemm_kernel(int sel, const float* __restrict__ W) {
    __shared__ __align__(16) float  As[BK][B];     // [k][b]  16 KB
    __shared__ __align__(16) float2 Ws[BK][BN];    // duplicated pairs  8 KB
    const float* xt = g_xt[sel];
    int jt = blockIdx.x;           // 0..95
    int ks = blockIdx.y;           // 0..3
    int n0 = jt * BN;
    int j0 = (n0 < H) ? n0 : n0 + H;
    float* out = g_part[ks];
    int tid = threadIdx.x;
    int tpy = tid & 15;            // batch-pair group: pairs tpy*4..+3 (rows tpy*8..+7)
    int tpx = tid >> 4;            // col group: cols tpx*2, tpx*2+1

    unsigned long long acc[2][4];
    #pragma unroll
    for (int j = 0; j < 2; j++)
        #pragma unroll
        for (int p = 0; p < 4; p++) acc[j][p] = 0ull;

    int k0base = ks * (H / KS);
    for (int kt = 0; kt < H / KS; kt += BK) {
        int k0 = k0base + kt;
        // stage A tile: 128 x 32 floats, transposed to [k][b]
        #pragma unroll
        for (int c = 0; c < 4; c++) {
            int chunk = tid + c * 256;           // 0..1023 float4 chunks
            int b = chunk >> 3, kf = chunk & 7;
            float4 v = *(const float4*)&xt[b*H + k0 + kf*4];
            As[kf*4+0][b] = v.x; As[kf*4+1][b] = v.y;
            As[kf*4+2][b] = v.z; As[kf*4+3][b] = v.w;
        }
        // stage W tile: 32 x 32 floats, duplicated into f32 pairs
        {
            int j = tid >> 3, kf = tid & 7;
            float4 v = *(const float4*)&W[(size_t)(j0 + j)*H + k0 + kf*4];
            Ws[kf*4+0][j] = make_float2(v.x, v.x);
            Ws[kf*4+1][j] = make_float2(v.y, v.y);
            Ws[kf*4+2][j] = make_float2(v.z, v.z);
            Ws[kf*4+3][j] = make_float2(v.w, v.w);
        }
        __syncthreads();
        #pragma unroll
        for (int kk = 0; kk < BK; kk++) {
            ulonglong2 a01 = *(const ulonglong2*)&As[kk][tpy*8];
            ulonglong2 a23 = *(const ulonglong2*)&As[kk][tpy*8 + 4];
            ulonglong2 w01 = *(const ulonglong2*)&Ws[kk][tpx*2];
            fma2(acc[0][0], a01.x, w01.x);
            fma2(acc[0][1], a01.y, w01.x);
            fma2(acc[0][2], a23.x, w01.x);
            fma2(acc[0][3], a23.y, w01.x);
            fma2(acc[1][0], a01.x, w01.y);
            fma2(acc[1][1], a01.y, w01.y);
            fma2(acc[1][2], a23.x, w01.y);
            fma2(acc[1][3], a23.y, w01.y);
        }
        __syncthreads();
    }
    // stage result through smem (reuse As) for coalesced global stores
    float (*Cs)[BN] = (float(*)[BN])As;
    #pragma unroll
    for (int j = 0; j < 2; j++) {
        #pragma unroll
        for (int p = 0; p < 4; p++) {
            float2 v = *(float2*)&acc[j][p];
            Cs[tpy*8 + p*2 + 0][tpx*2 + j] = v.x;
            Cs[tpy*8 + p*2 + 1][tpx*2 + j] = v.y;
        }
    }
    __syncthreads();
    #pragma unroll
    for (int c = 0; c < 4; c++) {
        int chunk = tid + c * 256;
        int b = chunk >> 3, f = chunk & 7;
        *(float4*)&out[b*NCOL + n0 + f*4] = *(const float4*)&Cs[b][f*4];
    }
}

// ---------------- 5) activation + state writes ----------------------------
__device__ __forceinline__ float sigmoidf_(float v) { return 1.0f / (1.0f + expf(-v)); }

__global__ void act_kernel(int l, int sel,
                           const float* __restrict__ b_ih,
                           const float* __restrict__ b_hh,
                           float* __restrict__ out) {
    int idx = blockIdx.x * blockDim.x + threadIdx.x;   // 0..131071
    int b = idx >> 10;
    int u = idx & (H - 1);
    float gi = 0.f, gg = 0.f, go = 0.f;
    #pragma unroll
    for (int ks = 0; ks < KS; ks++) {
        gi += g_part[ks][b*NCOL + u];
        gg += g_part[ks][b*NCOL + H + u];
        go += g_part[ks][b*NCOL + 2*H + u];
    }
    const float* bi = b_ih + l*4*H;
    const float* bh = b_hh + l*4*H;
    gi += bi[u]       + bh[u];
    gg += bi[2*H + u] + bh[2*H + u];
    go += bi[3*H + u] + bh[3*H + u];
    float c = sigmoidf_(gi) * tanhf(gg);
    float h = sigmoidf_(go) * tanhf(c);
    g_xt[sel ^ 1][b*H + u] = h;
    float m = (b < g_bslast) ? 1.0f : 0.0f;
    out[OUT_SH + (l*B + b)*H + u] = h * m;
    out[OUT_SC + (l*B + b)*H + u] = c * m;
}

// ---------------- 6) broadcast output [T, B, H] ----------------------------
__global__ void out_kernel(int sel, float* __restrict__ out) {
    int t = blockIdx.x;      // 0..511
    int b = blockIdx.y;      // 0..127
    int q = threadIdx.x;     // 256 threads, float4 each
    float4 v = make_float4(0.f, 0.f, 0.f, 0.f);
    if (t < g_len[b]) {
        v = *(const float4*)&g_xt[sel][g_rank[b]*H + q*4];
    }
    *(float4*)&out[(size_t)(t*B + b)*H + q*4] = v;
}

// ---------------- launcher -------------------------------------------------
extern "C" void kernel_launch(void* const* d_in, const int* in_sizes, int n_in,
                              void* d_out, int out_size) {
    const int*   x    = (const int*)d_in[0];
    const float* emb  = (const float*)d_in[1];
    const float* W_ih = (const float*)d_in[2];
    // d_in[3] = W_hh: multiplied by h0 == 0, never read
    const float* b_ih = (const float*)d_in[4];
    const float* b_hh = (const float*)d_in[5];
    float* out = (float*)d_out;

    len_kernel<<<B, 32>>>(x);
    sort_kernel<<<1, B>>>(x);
    embed_kernel<<<B, 256>>>(emb);

    int sel = 0;
    for (int l = 0; l < NL; l++) {
        dim3 grid(NCOL / BN, KS);
        gemm_kernel<<<grid, 256>>>(sel, W_ih + (size_t)l * 4 * H * H);
        act_kernel<<<(B * H) / 256, 256>>>(l, sel, b_ih, b_hh, out);
        sel ^= 1;
    }
    out_kernel<<<dim3(S, B), 256>>>(sel, out);
}

// round 3
// speedup vs baseline: 2.0214x; 2.0214x over previous
#include <cuda_runtime.h>

#define B 128
#define S 512
#define H 1024
#define NL 4
#define NCOL 3072      // only i,g,o gate blocks (f-gate dead: c0 = 0; W_hh dead: h0 = 0)
#define KS 6           // K-split -> 24 x 6 = 144 CTAs = one full wave
#define BM 128
#define BN 128
#define BK 16

#define OUT_SH (S*B*H)            // 67108864
#define OUT_SC (S*B*H + NL*B*H)   // 67633152

// ---------------- scratch (device globals; no allocation allowed) ----------
__device__ float g_xt[2][B*H];          // ping-pong layer activations (sorted order)
__device__ float g_part[KS][NCOL*B];    // K-split GEMM partials, [n][b]-major
__device__ int   g_len[B];
__device__ int   g_rank[B];
__device__ int   g_sorted[B];
__device__ int   g_tok0[B];
__device__ int   g_bslast;

// ---------------- packed fp32x2 FMA (PTX-only on Blackwell) ----------------
__device__ __forceinline__ void fma2(unsigned long long &d,
                                     unsigned long long a,
                                     unsigned long long b) {
    asm("fma.rn.f32x2 %0, %1, %2, %0;" : "+l"(d) : "l"(a), "l"(b));
}

// ---------------- 1) lengths ----------------------------------------------
__global__ void len_kernel(const int* __restrict__ x) {
    int b = blockIdx.x, lane = threadIdx.x;
    int cnt = 0;
    #pragma unroll
    for (int s = lane; s < S; s += 32) cnt += (x[b*S + s] > 0);
    #pragma unroll
    for (int o = 16; o; o >>= 1) cnt += __shfl_down_sync(0xffffffffu, cnt, o);
    if (lane == 0) g_len[b] = cnt;
}

// ---------------- 2) stable descending argsort of 128 lengths -------------
__global__ void sort_kernel(const int* __restrict__ x) {
    __shared__ int slen[B];
    __shared__ int ssort[B];
    int b = threadIdx.x;
    slen[b] = g_len[b];
    __syncthreads();
    int lb = slen[b];
    int rank = 0, bs = 0;
    #pragma unroll 8
    for (int i = 0; i < B; i++) {
        int li = slen[i];
        rank += (li > lb) || (li == lb && i < b);
        bs += (li >= S);
    }
    g_rank[b] = rank;
    ssort[rank] = b;
    if (b == 0) g_bslast = bs;
    __syncthreads();
    int src = ssort[b];
    g_sorted[b] = src;
    g_tok0[b] = x[src * S];
}

// ---------------- 3) embedding gather (sorted order) ----------------------
__global__ void embed_kernel(const float* __restrict__ emb) {
    int i = blockIdx.x;
    int t = threadIdx.x;       // 256 threads, 1 float4 each (H = 1024)
    int tok = g_tok0[i];
    *(float4*)&g_xt[0][i*H + t*4] = *(const float4*)&emb[tok*H + t*4];
}

// ---------------- 4) GEMM: part[n][b] += xt[b,:] . W[j(n),:] --------------
// 128x128 block tile, 8x8 thread tile via f32x2, double-buffered smem.
__global__ __launch_bounds__(256, 1) void gemm_kernel(int sel, const float* __restrict__ W) {
    __shared__ __align__(16) float  As[2][BK][BM];   // 16 KB  [k][b]
    __shared__ __align__(16) float2 Ws[2][BK][BN];   // 32 KB  duplicated pairs
    const float* __restrict__ xt = g_xt[sel];
    const int nt = blockIdx.x;            // 0..23
    const int ks = blockIdx.y;            // 0..5
    const int n0 = nt * BN;
    const int j0 = (n0 < H) ? n0 : n0 + H;        // skip dead f-gate rows
    const int cnt = 11 - (ks >= 4);               // BK-steps this split
    const int t0  = ks * 11 - (ks == 5 ? 1 : 0);  // {0,11,22,33,44,54}
    const int tid = threadIdx.x;
    const int tpy = tid & 15;             // row group: rows tpy*8..+7
    const int tpx = tid >> 4;             // col group: cols tpx*8..+7
    const int cb  = tid >> 2;             // stage row (0..63), +64 for 2nd chunk
    const int ckf = tid & 3;              // stage float4 index in k

    unsigned long long acc[4][8];
    #pragma unroll
    for (int p = 0; p < 4; p++)
        #pragma unroll
        for (int j = 0; j < 8; j++) acc[p][j] = 0ull;

    float4 ra0, ra1, rw0, rw1;
    {
        int k0 = t0 * BK;
        ra0 = *(const float4*)&xt[cb*H + k0 + ckf*4];
        ra1 = *(const float4*)&xt[(cb+64)*H + k0 + ckf*4];
        rw0 = *(const float4*)&W[(size_t)(j0+cb)*H + k0 + ckf*4];
        rw1 = *(const float4*)&W[(size_t)(j0+cb+64)*H + k0 + ckf*4];
    }

#define STORE_TILE(nb) do {                                                     \
    As[nb][ckf*4+0][cb]    = ra0.x; As[nb][ckf*4+1][cb]    = ra0.y;             \
    As[nb][ckf*4+2][cb]    = ra0.z; As[nb][ckf*4+3][cb]    = ra0.w;             \
    As[nb][ckf*4+0][cb+64] = ra1.x; As[nb][ckf*4+1][cb+64] = ra1.y;             \
    As[nb][ckf*4+2][cb+64] = ra1.z; As[nb][ckf*4+3][cb+64] = ra1.w;             \
    Ws[nb][ckf*4+0][cb]    = make_float2(rw0.x, rw0.x);                         \
    Ws[nb][ckf*4+1][cb]    = make_float2(rw0.y, rw0.y);                         \
    Ws[nb][ckf*4+2][cb]    = make_float2(rw0.z, rw0.z);                         \
    Ws[nb][ckf*4+3][cb]    = make_float2(rw0.w, rw0.w);                         \
    Ws[nb][ckf*4+0][cb+64] = make_float2(rw1.x, rw1.x);                         \
    Ws[nb][ckf*4+1][cb+64] = make_float2(rw1.y, rw1.y);                         \
    Ws[nb][ckf*4+2][cb+64] = make_float2(rw1.z, rw1.z);                         \
    Ws[nb][ckf*4+3][cb+64] = make_float2(rw1.w, rw1.w);                         \
} while (0)

    STORE_TILE(0);
    __syncthreads();

    for (int t = 0; t < cnt; t++) {
        int buf = t & 1;
        if (t + 1 < cnt) {
            int k0 = (t0 + t + 1) * BK;
            ra0 = *(const float4*)&xt[cb*H + k0 + ckf*4];
            ra1 = *(const float4*)&xt[(cb+64)*H + k0 + ckf*4];
            rw0 = *(const float4*)&W[(size_t)(j0+cb)*H + k0 + ckf*4];
            rw1 = *(const float4*)&W[(size_t)(j0+cb+64)*H + k0 + ckf*4];
        }
        #pragma unroll
        for (int kk = 0; kk < BK; kk++) {
            ulonglong2 a01 = *(const ulonglong2*)&As[buf][kk][tpy*8];
            ulonglong2 a23 = *(const ulonglong2*)&As[buf][kk][tpy*8 + 4];
            const ulonglong2* wrow = (const ulonglong2*)&Ws[buf][kk][tpx*8];
            ulonglong2 w01 = wrow[0];
            ulonglong2 w23 = wrow[1];
            ulonglong2 w45 = wrow[2];
            ulonglong2 w67 = wrow[3];
            fma2(acc[0][0], a01.x, w01.x); fma2(acc[1][0], a01.y, w01.x);
            fma2(acc[2][0], a23.x, w01.x); fma2(acc[3][0], a23.y, w01.x);
            fma2(acc[0][1], a01.x, w01.y); fma2(acc[1][1], a01.y, w01.y);
            fma2(acc[2][1], a23.x, w01.y); fma2(acc[3][1], a23.y, w01.y);
            fma2(acc[0][2], a01.x, w23.x); fma2(acc[1][2], a01.y, w23.x);
            fma2(acc[2][2], a23.x, w23.x); fma2(acc[3][2], a23.y, w23.x);
            fma2(acc[0][3], a01.x, w23.y); fma2(acc[1][3], a01.y, w23.y);
            fma2(acc[2][3], a23.x, w23.y); fma2(acc[3][3], a23.y, w23.y);
            fma2(acc[0][4], a01.x, w45.x); fma2(acc[1][4], a01.y, w45.x);
            fma2(acc[2][4], a23.x, w45.x); fma2(acc[3][4], a23.y, w45.x);
            fma2(acc[0][5], a01.x, w45.y); fma2(acc[1][5], a01.y, w45.y);
            fma2(acc[2][5], a23.x, w45.y); fma2(acc[3][5], a23.y, w45.y);
            fma2(acc[0][6], a01.x, w67.x); fma2(acc[1][6], a01.y, w67.x);
            fma2(acc[2][6], a23.x, w67.x); fma2(acc[3][6], a23.y, w67.x);
            fma2(acc[0][7], a01.x, w67.y); fma2(acc[1][7], a01.y, w67.y);
            fma2(acc[2][7], a23.x, w67.y); fma2(acc[3][7], a23.y, w67.y);
        }
        if (t + 1 < cnt) {
            __syncthreads();
            STORE_TILE(buf ^ 1);
            __syncthreads();
        }
    }

    // epilogue: [n][b]-major, fully coalesced float4 stores
    float* out = g_part[ks];
    #pragma unroll
    for (int j = 0; j < 8; j++) {
        int n = n0 + tpx*8 + j;
        float2 f0 = *(float2*)&acc[0][j];
        float2 f1 = *(float2*)&acc[1][j];
        float2 f2 = *(float2*)&acc[2][j];
        float2 f3 = *(float2*)&acc[3][j];
        *(float4*)&out[n*B + tpy*8]     = make_float4(f0.x, f0.y, f1.x, f1.y);
        *(float4*)&out[n*B + tpy*8 + 4] = make_float4(f2.x, f2.y, f3.x, f3.y);
    }
#undef STORE_TILE
}

// ---------------- 5) activation + state writes ----------------------------
__device__ __forceinline__ float sigmoidf_(float v) { return 1.0f / (1.0f + expf(-v)); }

__global__ void act_kernel(int l, int sel,
                           const float* __restrict__ b_ih,
                           const float* __restrict__ b_hh,
                           float* __restrict__ out) {
    int idx = blockIdx.x * blockDim.x + threadIdx.x;   // 0..131071
    int b = idx & (B - 1);          // fast -> coalesced partial reads
    int u = idx >> 7;
    float gi = 0.f, gg = 0.f, go = 0.f;
    #pragma unroll
    for (int ks = 0; ks < KS; ks++) {
        const float* p = g_part[ks];
        gi += p[u*B + b];
        gg += p[(H + u)*B + b];
        go += p[(2*H + u)*B + b];
    }
    const float* bi = b_ih + l*4*H;
    const float* bh = b_hh + l*4*H;
    gi += bi[u]       + bh[u];
    gg += bi[2*H + u] + bh[2*H + u];
    go += bi[3*H + u] + bh[3*H + u];
    float c = sigmoidf_(gi) * tanhf(gg);
    float h = sigmoidf_(go) * tanhf(c);
    g_xt[sel ^ 1][b*H + u] = h;
    float m = (b < g_bslast) ? 1.0f : 0.0f;
    out[OUT_SH + (l*B + b)*H + u] = h * m;
    out[OUT_SC + (l*B + b)*H + u] = c * m;
}

// ---------------- 6) broadcast output [T, B, H] ----------------------------
__global__ void out_kernel(int sel, float* __restrict__ out) {
    int t = blockIdx.x;      // 0..511
    int b = blockIdx.y;      // 0..127
    int q = threadIdx.x;     // 256 threads, float4 each
    float4 v = make_float4(0.f, 0.f, 0.f, 0.f);
    if (t < g_len[b]) {
        v = *(const float4*)&g_xt[sel][g_rank[b]*H + q*4];
    }
    *(float4*)&out[(size_t)(t*B + b)*H + q*4] = v;
}

// ---------------- launcher -------------------------------------------------
extern "C" void kernel_launch(void* const* d_in, const int* in_sizes, int n_in,
                              void* d_out, int out_size) {
    const int*   x    = (const int*)d_in[0];
    const float* emb  = (const float*)d_in[1];
    const float* W_ih = (const float*)d_in[2];
    // d_in[3] = W_hh: multiplied by h0 == 0, never read
    const float* b_ih = (const float*)d_in[4];
    const float* b_hh = (const float*)d_in[5];
    float* out = (float*)d_out;

    len_kernel<<<B, 32>>>(x);
    sort_kernel<<<1, B>>>(x);
    embed_kernel<<<B, 256>>>(emb);

    int sel = 0;
    for (int l = 0; l < NL; l++) {
        dim3 grid(NCOL / BN, KS);
        gemm_kernel<<<grid, 256>>>(sel, W_ih + (size_t)l * 4 * H * H);
        act_kernel<<<(B * H) / 256, 256>>>(l, sel, b_ih, b_hh, out);
        sel ^= 1;
    }
    out_kernel<<<dim3(S, B), 256>>>(sel, out);
}

// round 5
// speedup vs baseline: 3.4598x; 1.7115x over previous
#include <cuda_runtime.h>
#include <cstdint>
#include <cstddef>

#define B 128
#define S 512
#define H 1024
#define NL 4
#define NCOL 3072      // only i,g,o gate blocks (f dead: c0=0; W_hh dead: h0=0)
#define KSPL 6         // K splits -> 24 x 6 = 144 CTAs = one wave
#define NT 24          // N tiles of 128
#define BN 128
#define KC 32          // k-floats per smem chunk
#define PAD 36         // row pitch in floats (36 = 4 mod 32 -> conflict-free)

#define OUT_SH (S*B*H)            // 67108864
#define OUT_SC (S*B*H + NL*B*H)   // 67633152

// smem float offsets: X bufs then W bufs, each 128*PAD floats
#define XOFF(buf) ((buf) * (128*PAD))
#define WOFF(buf) (2*(128*PAD) + (buf) * (128*PAD))
#define SM_FLOATS (4*(128*PAD))                 // 18432 floats = 73728 B

// ---------------- scratch (device globals; no allocation allowed) ----------
__device__ __align__(16) float g_xt[2][B*H];
__device__ __align__(16) float g_part[KSPL][NCOL*B];   // [n][b]-major partials
__device__ int g_len[B];
__device__ int g_rank[B];
__device__ int g_sorted[B];
__device__ int g_tok0[B];
__device__ int g_bslast;

// ---------------- PTX helpers ----------------------------------------------
__device__ __forceinline__ uint32_t smem_u32(const void* p) {
    uint32_t a;
    asm("{ .reg .u64 t; cvta.to.shared.u64 t, %1; cvt.u32.u64 %0, t; }" : "=r"(a) : "l"(p));
    return a;
}
__device__ __forceinline__ uint32_t f2tf32(float x) {
    uint32_t u;
    asm("cvt.rna.tf32.f32 %0, %1;" : "=r"(u) : "f"(x));
    return u;
}
__device__ __forceinline__ void ldsm_x4(uint32_t* r, uint32_t addr) {
    asm volatile("ldmatrix.sync.aligned.m8n8.x4.shared.b16 {%0,%1,%2,%3}, [%4];"
                 : "=r"(r[0]), "=r"(r[1]), "=r"(r[2]), "=r"(r[3]) : "r"(addr));
}
__device__ __forceinline__ void mma_tf32(float* d, const uint32_t* a,
                                         uint32_t b0, uint32_t b1) {
    asm volatile(
        "mma.sync.aligned.m16n8k8.row.col.f32.tf32.tf32.f32 "
        "{%0,%1,%2,%3}, {%4,%5,%6,%7}, {%8,%9}, {%0,%1,%2,%3};"
        : "+f"(d[0]), "+f"(d[1]), "+f"(d[2]), "+f"(d[3])
        : "r"(a[0]), "r"(a[1]), "r"(a[2]), "r"(a[3]), "r"(b0), "r"(b1));
}

// ---------------- 1) lengths ----------------------------------------------
__global__ void len_kernel(const int* __restrict__ x) {
    int b = blockIdx.x, lane = threadIdx.x;
    int cnt = 0;
    #pragma unroll
    for (int s = lane; s < S; s += 32) cnt += (x[b*S + s] > 0);
    #pragma unroll
    for (int o = 16; o; o >>= 1) cnt += __shfl_down_sync(0xffffffffu, cnt, o);
    if (lane == 0) g_len[b] = cnt;
}

// ---------------- 2) stable descending argsort of 128 lengths -------------
__global__ void sort_kernel(const int* __restrict__ x) {
    __shared__ int slen[B];
    __shared__ int ssort[B];
    int b = threadIdx.x;
    slen[b] = g_len[b];
    __syncthreads();
    int lb = slen[b];
    int rank = 0, bs = 0;
    #pragma unroll 8
    for (int i = 0; i < B; i++) {
        int li = slen[i];
        rank += (li > lb) || (li == lb && i < b);
        bs += (li >= S);
    }
    g_rank[b] = rank;
    ssort[rank] = b;
    if (b == 0) g_bslast = bs;
    __syncthreads();
    int src = ssort[b];
    g_sorted[b] = src;
    g_tok0[b] = x[src * S];
}

// ---------------- 3) embedding gather (sorted order) ----------------------
__global__ void embed_kernel(const float* __restrict__ emb) {
    int i = blockIdx.x;
    int t = threadIdx.x;       // 256 threads, 1 float4 each (H = 1024)
    int tok = g_tok0[i];
    *(float4*)&g_xt[0][i*H + t*4] = *(const float4*)&emb[tok*H + t*4];
}

// ---------------- 4) tf32 mma.sync GEMM -----------------------------------
// part[ks][n][b] = sum_{k in split} xt[b][k] * W[j(n)][k]
// mma-"A" = W (row-major n x k, via ldmatrix b16 trick), mma-"B" = xt (col-major k x b)
__global__ __launch_bounds__(256, 1)
void gemm_mma(int sel, const float* __restrict__ W) {
    extern __shared__ __align__(16) float sm[];
    const uint32_t sb = smem_u32(sm);
    const int tid  = threadIdx.x;
    const int lane = tid & 31;
    const int warp = tid >> 5;
    const int wn = warp & 1;              // n half: 0/1
    const int wb = warp >> 1;             // b quarter: 0..3
    const int nt_ = blockIdx.x;           // 0..23
    const int ksp = blockIdx.y;           // 0..5
    const int n0 = nt_ * BN;
    const int j0 = (n0 < H) ? n0 : n0 + H;        // skip dead f-gate rows
    const int cnt = (ksp < 2) ? 6 : 5;            // chunks ({6,6,5,5,5,5} of 32)
    const int c0  = (ksp < 2) ? ksp*6 : 12 + (ksp-2)*5;
    const float* __restrict__ xt = g_xt[sel];

    // staging indices: thread handles float4-chunks f = tid + i*256
    const int sb_row = tid >> 3;          // 0..31 then +32.. via i
    const int sb_kq  = tid & 7;

    // ldmatrix lane address pieces (W operand)
    const int row_in = (lane & 7) + ((lane >> 3) & 1) * 8;
    const int kadd   = (lane >> 4) * 4;
    const int n0w    = wn * 64;
    const int b0w    = wb * 32;

    float acc[4][4][4];
    #pragma unroll
    for (int nt = 0; nt < 4; nt++)
        #pragma unroll
        for (int bt = 0; bt < 4; bt++)
            #pragma unroll
            for (int q = 0; q < 4; q++) acc[nt][bt][q] = 0.f;

    float4 xv[4], wv[4];
    {
        const int k0 = c0 * KC;
        #pragma unroll
        for (int i = 0; i < 4; i++) {
            int b = sb_row + i*32;
            xv[i] = *(const float4*)&xt[(size_t)b*H + k0 + sb_kq*4];
            wv[i] = *(const float4*)&W[(size_t)(j0 + b)*H + k0 + sb_kq*4];
        }
    }

#define STORE_TILE(buf) do {                                                    \
    _Pragma("unroll")                                                           \
    for (int i = 0; i < 4; i++) {                                               \
        int b = sb_row + i*32;                                                  \
        uint4 xc = make_uint4(f2tf32(xv[i].x), f2tf32(xv[i].y),                 \
                              f2tf32(xv[i].z), f2tf32(xv[i].w));                \
        uint4 wc = make_uint4(f2tf32(wv[i].x), f2tf32(wv[i].y),                 \
                              f2tf32(wv[i].z), f2tf32(wv[i].w));                \
        *(uint4*)&sm[XOFF(buf) + b*PAD + sb_kq*4] = xc;                         \
        *(uint4*)&sm[WOFF(buf) + b*PAD + sb_kq*4] = wc;                         \
    }                                                                           \
} while (0)

    STORE_TILE(0);
    __syncthreads();

    for (int t = 0; t < cnt; t++) {
        const int buf = t & 1;
        if (t + 1 < cnt) {
            const int k0 = (c0 + t + 1) * KC;
            #pragma unroll
            for (int i = 0; i < 4; i++) {
                int b = sb_row + i*32;
                xv[i] = *(const float4*)&xt[(size_t)b*H + k0 + sb_kq*4];
                wv[i] = *(const float4*)&W[(size_t)(j0 + b)*H + k0 + sb_kq*4];
            }
        }
        const uint32_t wbase = sb + (WOFF(buf) + (n0w + row_in)*PAD + kadd) * 4;
        const int      xbase = XOFF(buf) + (b0w + (lane >> 2))*PAD + (lane & 3);
        #pragma unroll
        for (int kk = 0; kk < 4; kk++) {          // 4 k-steps of 8
            uint32_t a[4][4];
            #pragma unroll
            for (int nt = 0; nt < 4; nt++)
                ldsm_x4(a[nt], wbase + (nt*16*PAD + kk*8) * 4);
            uint32_t bb[4][2];
            #pragma unroll
            for (int bt = 0; bt < 4; bt++) {
                bb[bt][0] = __float_as_uint(sm[xbase + bt*8*PAD + kk*8]);
                bb[bt][1] = __float_as_uint(sm[xbase + bt*8*PAD + kk*8 + 4]);
            }
            #pragma unroll
            for (int nt = 0; nt < 4; nt++)
                #pragma unroll
                for (int bt = 0; bt < 4; bt++)
                    mma_tf32(acc[nt][bt], a[nt], bb[bt][0], bb[bt][1]);
        }
        if (t + 1 < cnt) {
            __syncthreads();
            STORE_TILE(buf ^ 1);
            __syncthreads();
        }
    }
#undef STORE_TILE

    // epilogue: D rows = n, cols = b -> [n][b]-major partial stores
    float* outp = g_part[ksp];
    const int nrow = n0 + n0w + (lane >> 2);
    const int bcol = b0w + 2*(lane & 3);
    #pragma unroll
    for (int nt = 0; nt < 4; nt++) {
        #pragma unroll
        for (int bt = 0; bt < 4; bt++) {
            int n = nrow + nt*16;
            int b = bcol + bt*8;
            *(float2*)&outp[(size_t)n*B + b]     = make_float2(acc[nt][bt][0], acc[nt][bt][1]);
            *(float2*)&outp[(size_t)(n+8)*B + b] = make_float2(acc[nt][bt][2], acc[nt][bt][3]);
        }
    }
}

// ---------------- 5) activation + state writes ----------------------------
__device__ __forceinline__ float sigmoidf_(float v) { return 1.0f / (1.0f + expf(-v)); }

__global__ void act_kernel(int l, int sel,
                           const float* __restrict__ b_ih,
                           const float* __restrict__ b_hh,
                           float* __restrict__ out) {
    int idx = blockIdx.x * blockDim.x + threadIdx.x;   // 0..131071
    int b = idx & (B - 1);          // fast -> coalesced partial reads
    int u = idx >> 7;
    float gi = 0.f, gg = 0.f, go = 0.f;
    #pragma unroll
    for (int ks = 0; ks < KSPL; ks++) {
        const float* p = g_part[ks];
        gi += p[u*B + b];
        gg += p[(H + u)*B + b];
        go += p[(2*H + u)*B + b];
    }
    const float* bi = b_ih + l*4*H;
    const float* bh = b_hh + l*4*H;
    gi += bi[u]       + bh[u];
    gg += bi[2*H + u] + bh[2*H + u];
    go += bi[3*H + u] + bh[3*H + u];
    float c = sigmoidf_(gi) * tanhf(gg);
    float h = sigmoidf_(go) * tanhf(c);
    g_xt[sel ^ 1][b*H + u] = h;
    float m = (b < g_bslast) ? 1.0f : 0.0f;
    out[OUT_SH + (l*B + b)*H + u] = h * m;
    out[OUT_SC + (l*B + b)*H + u] = c * m;
}

// ---------------- 6) broadcast output [T, B, H] ----------------------------
__global__ void out_kernel(int sel, float* __restrict__ out) {
    int tg = blockIdx.x;     // 0..63 (groups of 8 t)
    int b  = blockIdx.y;     // 0..127
    int q  = threadIdx.x;    // 256 threads, float4 each
    int len = g_len[b];
    const float4 h = *(const float4*)&g_xt[sel][g_rank[b]*H + q*4];
    const float4 z = make_float4(0.f, 0.f, 0.f, 0.f);
    #pragma unroll
    for (int i = 0; i < 8; i++) {
        int t = tg*8 + i;
        float4 v = (t < len) ? h : z;
        __stcs((float4*)&out[(size_t)(t*B + b)*H + q*4], v);
    }
}

// ---------------- launcher -------------------------------------------------
extern "C" void kernel_launch(void* const* d_in, const int* in_sizes, int n_in,
                              void* d_out, int out_size) {
    const int*   x    = (const int*)d_in[0];
    const float* emb  = (const float*)d_in[1];
    const float* W_ih = (const float*)d_in[2];
    // d_in[3] = W_hh: multiplied by h0 == 0, never read
    const float* b_ih = (const float*)d_in[4];
    const float* b_hh = (const float*)d_in[5];
    float* out = (float*)d_out;

    cudaFuncSetAttribute(gemm_mma, cudaFuncAttributeMaxDynamicSharedMemorySize,
                         SM_FLOATS * (int)sizeof(float));

    len_kernel<<<B, 32>>>(x);
    sort_kernel<<<1, B>>>(x);
    embed_kernel<<<B, 256>>>(emb);

    int sel = 0;
    for (int l = 0; l < NL; l++) {
        dim3 grid(NT, KSPL);
        gemm_mma<<<grid, 256, SM_FLOATS * sizeof(float)>>>(sel, W_ih + (size_t)l * 4 * H * H);
        act_kernel<<<(B * H) / 256, 256>>>(l, sel, b_ih, b_hh, out);
        sel ^= 1;
    }
    out_kernel<<<dim3(S/8, B), 256>>>(sel, out);
}

// round 6
// speedup vs baseline: 3.4696x; 1.0028x over previous
#include <cuda_runtime.h>
#include <cstdint>
#include <cstddef>

#define B 128
#define S 512
#define H 1024
#define NL 4
#define NCOL 3072      // only i,g,o gate blocks (f dead: c0=0; W_hh dead: h0=0)
#define KSPL 6         // K splits -> 24 x 6 = 144 CTAs = one wave
#define NT 24          // N tiles of 128
#define BN 128
#define KC 32          // k-floats per smem chunk
#define PAD 36         // row pitch in floats (36 -> conflict-free LDS & ldmatrix)
#define STAGES 4

#define OUT_SH (S*B*H)            // 67108864
#define OUT_SC (S*B*H + NL*B*H)   // 67633152

// smem float offsets: per-stage [X(128*PAD) | W(128*PAD)]
#define STG   (2*128*PAD)
#define XOFF(s) ((s)*STG)
#define WOFF(s) ((s)*STG + 128*PAD)
#define SM_FLOATS (STAGES*STG)                 // 36864 floats = 147456 B

// ---------------- scratch (device globals; no allocation allowed) ----------
__device__ __align__(16) float g_xt[2][B*H];
__device__ __align__(16) float g_part[KSPL][NCOL*B];   // [n][b]-major partials
__device__ int g_len[B];
__device__ int g_rank[B];
__device__ int g_sorted[B];
__device__ int g_tok0[B];
__device__ int g_bslast;

// ---------------- PTX helpers ----------------------------------------------
__device__ __forceinline__ uint32_t smem_u32(const void* p) {
    uint32_t a;
    asm("{ .reg .u64 t; cvta.to.shared.u64 t, %1; cvt.u32.u64 %0, t; }" : "=r"(a) : "l"(p));
    return a;
}
__device__ __forceinline__ uint32_t f2tf32(float x) {
    uint32_t u;
    asm("cvt.rna.tf32.f32 %0, %1;" : "=r"(u) : "f"(x));
    return u;
}
__device__ __forceinline__ uint32_t bits2tf32(uint32_t r) {
    uint32_t u;
    asm("cvt.rna.tf32.f32 %0, %1;" : "=r"(u) : "f"(__uint_as_float(r)));
    return u;
}
__device__ __forceinline__ void cp16(uint32_t dst, const void* src) {
    asm volatile("cp.async.cg.shared.global [%0], [%1], 16;" :: "r"(dst), "l"(src));
}
#define CP_COMMIT() asm volatile("cp.async.commit_group;" ::: "memory")
#define CP_WAIT2()  asm volatile("cp.async.wait_group 2;" ::: "memory")

__device__ __forceinline__ void ldsm_x4(uint32_t* r, uint32_t addr) {
    asm volatile("ldmatrix.sync.aligned.m8n8.x4.shared.b16 {%0,%1,%2,%3}, [%4];"
                 : "=r"(r[0]), "=r"(r[1]), "=r"(r[2]), "=r"(r[3]) : "r"(addr));
}
__device__ __forceinline__ void mma_tf32(float* d, const uint32_t* a,
                                         uint32_t b0, uint32_t b1) {
    asm volatile(
        "mma.sync.aligned.m16n8k8.row.col.f32.tf32.tf32.f32 "
        "{%0,%1,%2,%3}, {%4,%5,%6,%7}, {%8,%9}, {%0,%1,%2,%3};"
        : "+f"(d[0]), "+f"(d[1]), "+f"(d[2]), "+f"(d[3])
        : "r"(a[0]), "r"(a[1]), "r"(a[2]), "r"(a[3]), "r"(b0), "r"(b1));
}

// ---------------- 1) lengths ----------------------------------------------
__global__ void len_kernel(const int* __restrict__ x) {
    int b = blockIdx.x, lane = threadIdx.x;
    int cnt = 0;
    #pragma unroll
    for (int s = lane; s < S; s += 32) cnt += (x[b*S + s] > 0);
    #pragma unroll
    for (int o = 16; o; o >>= 1) cnt += __shfl_down_sync(0xffffffffu, cnt, o);
    if (lane == 0) g_len[b] = cnt;
}

// ---------------- 2) stable descending argsort of 128 lengths -------------
__global__ void sort_kernel(const int* __restrict__ x) {
    __shared__ int slen[B];
    __shared__ int ssort[B];
    int b = threadIdx.x;
    slen[b] = g_len[b];
    __syncthreads();
    int lb = slen[b];
    int rank = 0, bs = 0;
    #pragma unroll 8
    for (int i = 0; i < B; i++) {
        int li = slen[i];
        rank += (li > lb) || (li == lb && i < b);
        bs += (li >= S);
    }
    g_rank[b] = rank;
    ssort[rank] = b;
    if (b == 0) g_bslast = bs;
    __syncthreads();
    int src = ssort[b];
    g_sorted[b] = src;
    g_tok0[b] = x[src * S];
}

// ---------------- 3) embedding gather (sorted order) ----------------------
__global__ void embed_kernel(const float* __restrict__ emb) {
    int i = blockIdx.x;
    int t = threadIdx.x;       // 256 threads, 1 float4 each (H = 1024)
    int tok = g_tok0[i];
    *(float4*)&g_xt[0][i*H + t*4] = *(const float4*)&emb[tok*H + t*4];
}

// ---------------- 4) tf32 mma.sync GEMM, cp.async 4-stage pipeline --------
// part[ks][n][b] = sum_{k in split} xt[b][k] * W[j(n)][k]
// mma-"A" = W (row-major n x k via ldmatrix b16 trick), mma-"B" = xt ([b][k])
__global__ __launch_bounds__(256, 1)
void gemm_mma(int sel, const float* __restrict__ W) {
    extern __shared__ __align__(16) float sm[];
    const uint32_t sb = smem_u32(sm);
    const int tid  = threadIdx.x;
    const int lane = tid & 31;
    const int warp = tid >> 5;
    const int wn = warp & 1;              // n half: 0/1
    const int wb = warp >> 1;             // b quarter: 0..3
    const int nt_ = blockIdx.x;           // 0..23
    const int ksp = blockIdx.y;           // 0..5
    const int n0 = nt_ * BN;
    const int j0 = (n0 < H) ? n0 : n0 + H;        // skip dead f-gate rows
    const int cnt = (ksp < 2) ? 6 : 5;            // chunks ({6,6,5,5,5,5} of 32)
    const int c0  = (ksp < 2) ? ksp*6 : 12 + (ksp-2)*5;
    const float* __restrict__ xt = g_xt[sel];

    // staging: thread covers rows sb_row + i*32, 16 B at k-offset sb_kq*4
    const int sb_row = tid >> 3;          // 0..31
    const int sb_kq  = tid & 7;

    // ldmatrix lane address pieces (W operand)
    const int row_in = (lane & 7) + ((lane >> 3) & 1) * 8;
    const int kadd   = (lane >> 4) * 4;
    const int n0w    = wn * 64;
    const int b0w    = wb * 32;

    float acc[4][4][4];
    #pragma unroll
    for (int nt = 0; nt < 4; nt++)
        #pragma unroll
        for (int bt = 0; bt < 4; bt++)
            #pragma unroll
            for (int q = 0; q < 4; q++) acc[nt][bt][q] = 0.f;

#define ISSUE_STAGE(s, c) do {                                                  \
    const int k0_ = (c0 + (c)) * KC;                                            \
    _Pragma("unroll")                                                           \
    for (int i = 0; i < 4; i++) {                                               \
        int b_ = sb_row + i*32;                                                 \
        cp16(sb + (XOFF(s) + b_*PAD + sb_kq*4)*4, &xt[(size_t)b_*H + k0_ + sb_kq*4]); \
        cp16(sb + (WOFF(s) + b_*PAD + sb_kq*4)*4, &W[(size_t)(j0 + b_)*H + k0_ + sb_kq*4]); \
    }                                                                           \
    CP_COMMIT();                                                                \
} while (0)

    // prologue: fire 3 stages (max MLP up front)
    ISSUE_STAGE(0, 0);
    ISSUE_STAGE(1, 1);
    ISSUE_STAGE(2, 2);

    for (int t = 0; t < cnt; t++) {
        const int buf = t & (STAGES - 1);
        CP_WAIT2();
        __syncthreads();

        const uint32_t wbase = sb + (WOFF(buf) + (n0w + row_in)*PAD + kadd) * 4;
        const int      xbase = XOFF(buf) + (b0w + (lane >> 2))*PAD + (lane & 3);
        #pragma unroll
        for (int kk = 0; kk < 4; kk++) {          // 4 k-steps of 8
            uint32_t a[4][4];
            #pragma unroll
            for (int nt = 0; nt < 4; nt++) {
                ldsm_x4(a[nt], wbase + (nt*16*PAD + kk*8) * 4);
                a[nt][0] = bits2tf32(a[nt][0]);
                a[nt][1] = bits2tf32(a[nt][1]);
                a[nt][2] = bits2tf32(a[nt][2]);
                a[nt][3] = bits2tf32(a[nt][3]);
            }
            uint32_t bb[4][2];
            #pragma unroll
            for (int bt = 0; bt < 4; bt++) {
                bb[bt][0] = f2tf32(sm[xbase + bt*8*PAD + kk*8]);
                bb[bt][1] = f2tf32(sm[xbase + bt*8*PAD + kk*8 + 4]);
            }
            #pragma unroll
            for (int nt = 0; nt < 4; nt++)
                #pragma unroll
                for (int bt = 0; bt < 4; bt++)
                    mma_tf32(acc[nt][bt], a[nt], bb[bt][0], bb[bt][1]);
        }
        __syncthreads();
        if (t + 3 < cnt) ISSUE_STAGE((t + 3) & (STAGES - 1), t + 3);
        else             CP_COMMIT();    // empty group keeps wait_group(2) aligned
    }
#undef ISSUE_STAGE

    // epilogue: D rows = n, cols = b -> [n][b]-major partial stores
    float* outp = g_part[ksp];
    const int nrow = n0 + n0w + (lane >> 2);
    const int bcol = b0w + 2*(lane & 3);
    #pragma unroll
    for (int nt = 0; nt < 4; nt++) {
        #pragma unroll
        for (int bt = 0; bt < 4; bt++) {
            int n = nrow + nt*16;
            int b = bcol + bt*8;
            *(float2*)&outp[(size_t)n*B + b]     = make_float2(acc[nt][bt][0], acc[nt][bt][1]);
            *(float2*)&outp[(size_t)(n+8)*B + b] = make_float2(acc[nt][bt][2], acc[nt][bt][3]);
        }
    }
}

// ---------------- 5) activation + state writes ----------------------------
__device__ __forceinline__ float sigmoidf_(float v) { return 1.0f / (1.0f + expf(-v)); }

__global__ void act_kernel(int l, int sel,
                           const float* __restrict__ b_ih,
                           const float* __restrict__ b_hh,
                           float* __restrict__ out) {
    int idx = blockIdx.x * blockDim.x + threadIdx.x;   // 0..131071
    int b = idx & (B - 1);          // fast -> coalesced partial reads
    int u = idx >> 7;
    float gi = 0.f, gg = 0.f, go = 0.f;
    #pragma unroll
    for (int ks = 0; ks < KSPL; ks++) {
        const float* p = g_part[ks];
        gi += p[u*B + b];
        gg += p[(H + u)*B + b];
        go += p[(2*H + u)*B + b];
    }
    const float* bi = b_ih + l*4*H;
    const float* bh = b_hh + l*4*H;
    gi += bi[u]       + bh[u];
    gg += bi[2*H + u] + bh[2*H + u];
    go += bi[3*H + u] + bh[3*H + u];
    float c = sigmoidf_(gi) * tanhf(gg);
    float h = sigmoidf_(go) * tanhf(c);
    g_xt[sel ^ 1][b*H + u] = h;
    float m = (b < g_bslast) ? 1.0f : 0.0f;
    out[OUT_SH + (l*B + b)*H + u] = h * m;
    out[OUT_SC + (l*B + b)*H + u] = c * m;
}

// ---------------- 6) broadcast output [T, B, H] ----------------------------
__global__ void out_kernel(int sel, float* __restrict__ out) {
    int tg = blockIdx.x;     // 0..63 (groups of 8 t)
    int b  = blockIdx.y;     // 0..127
    int q  = threadIdx.x;    // 256 threads, float4 each
    int len = g_len[b];
    const float4 h = *(const float4*)&g_xt[sel][g_rank[b]*H + q*4];
    const float4 z = make_float4(0.f, 0.f, 0.f, 0.f);
    #pragma unroll
    for (int i = 0; i < 8; i++) {
        int t = tg*8 + i;
        float4 v = (t < len) ? h : z;
        __stcs((float4*)&out[(size_t)(t*B + b)*H + q*4], v);
    }
}

// ---------------- launcher -------------------------------------------------
extern "C" void kernel_launch(void* const* d_in, const int* in_sizes, int n_in,
                              void* d_out, int out_size) {
    const int*   x    = (const int*)d_in[0];
    const float* emb  = (const float*)d_in[1];
    const float* W_ih = (const float*)d_in[2];
    // d_in[3] = W_hh: multiplied by h0 == 0, never read
    const float* b_ih = (const float*)d_in[4];
    const float* b_hh = (const float*)d_in[5];
    float* out = (float*)d_out;

    cudaFuncSetAttribute(gemm_mma, cudaFuncAttributeMaxDynamicSharedMemorySize,
                         SM_FLOATS * (int)sizeof(float));

    len_kernel<<<B, 32>>>(x);
    sort_kernel<<<1, B>>>(x);
    embed_kernel<<<B, 256>>>(emb);

    int sel = 0;
    for (int l = 0; l < NL; l++) {
        dim3 grid(NT, KSPL);
        gemm_mma<<<grid, 256, SM_FLOATS * sizeof(float)>>>(sel, W_ih + (size_t)l * 4 * H * H);
        act_kernel<<<(B * H) / 256, 256>>>(l, sel, b_ih, b_hh, out);
        sel ^= 1;
    }
    out_kernel<<<dim3(S/8, B), 256>>>(sel, out);
}